// round 16
// baseline (speedup 1.0000x reference)
#include <cuda_runtime.h>

// ANFIS_61280593380167 — B=8192, D=256, R=64, O=256, fp32.
//
// out[b,o] = sum_r f[b,r] * (x[b,:] @ W[r] + b[r])
// f[b,r]   = frs[b,r] / (sum_r frs[b,r] + 1e-8),  frs = exp(-sum (x-mu)^2/(2 sig^2))
//
// frs underflows to exact fp32 zero for ~99% of (b,r) pairs (as in the
// reference); zero f contributes exactly zero. Compute f, compact nonzero
// (b,f) pairs per rule, build a worklist (fused into memb's last block),
// process with persistent expert blocks.
//
// memb uses pack-free fma.rn.f32x2: coefficients pre-stored as (-a,-a,b2,b2)
// so one LDG.128 yields two packed operands; x row-pairs come packed from the
// transposed SMEM tile. IEEE fp32 per lane — bit-identical math.
// Expert kernel is the empirically best configuration (R8: 39.8us, regs 75,
// IUNR=16 double-buffered prefetch, dynamic queue). Do not touch.

#define B_SZ 8192
#define D_SZ 256
#define R_SZ 64
#define O_SZ 256
#define MCH   16     // batch rows per expert chunk
#define XPAD  20     // x-tile stride (floats) in expert (16B-aligned rows)
#define MROWS 16     // batch rows per memb block (512 blocks)
#define MPAD  20     // x-tile stride (floats) in memb (16B-aligned rows)
#define IUNR  16     // W prefetch depth (double-buffered groups)
#define EGRID 1184   // persistent expert blocks

typedef unsigned long long ull;

// Scratch (__device__ globals: allocation-free rule)
__device__ int    g_count[R_SZ];
__device__ int    g_lb[R_SZ][B_SZ];
__device__ float  g_lf[R_SZ][B_SZ];
__device__ float4 g_coef[D_SZ * R_SZ]; // (-a, -a, b2, b2); a=1/(2s^2), b2=2 mu a
__device__ float  g_c [R_SZ];          // sum_i mu^2 a
__device__ int    g_work[R_SZ * (B_SZ / MCH) * 2];
__device__ int    g_nwork;
__device__ int    g_fetch;
__device__ int    g_done;

// ---- packed f32x2 helpers (no packing needed at use sites) -----------------
__device__ __forceinline__ ull fma2(ull a, ull b, ull c) {
    ull d;
    asm("fma.rn.f32x2 %0, %1, %2, %3;" : "=l"(d) : "l"(a), "l"(b), "l"(c));
    return d;
}
__device__ __forceinline__ float2 unpack2(ull v) {
    float2 f;
    asm("mov.b64 {%0, %1}, %2;" : "=f"(f.x), "=f"(f.y) : "l"(v));
    return f;
}

// ---------------------------------------------------------------------------
// Prep only: coefficients + counter reset. grid = 64 (one block per rule).
// ---------------------------------------------------------------------------
__global__ __launch_bounds__(256) void setup_kernel(
    const float* __restrict__ mu, const float* __restrict__ sig)
{
    const int r = blockIdx.x, i = threadIdx.x;

    if (r == 0) {
        if (i >= 192 && i < 192 + R_SZ) g_count[i - 192] = 0;
        if (i == 128) { g_nwork = 0; g_fetch = 0; g_done = 0; }
    }

    const float m = mu [i * R_SZ + r];
    const float s = sig[i * R_SZ + r];
    const float a = 0.5f / (s * s);
    g_coef[i * R_SZ + r] = make_float4(-a, -a, 2.0f * m * a, 2.0f * m * a);

    __shared__ float red[256];
    red[i] = m * m * a;
    __syncthreads();
    #pragma unroll
    for (int st = 128; st > 0; st >>= 1) {
        if (i < st) red[i] += red[i + st];
        __syncthreads();
    }
    if (i == 0) g_c[r] = red[0];
}

// ---------------------------------------------------------------------------
// Memberships + normalization + compaction + out-zeroing. 16 rows / block.
// Per i: 1 LDG.128 (packed coef pair) + 1 LDS.128 (two packed x pairs)
// + 4 FFMA2 (= 8 fp32 FMAs for 4 rows). Also zeroes its 16-row out slice
// (must complete before expert launch — guaranteed by kernel boundary).
// Last block to retire builds the expert worklist.
// ---------------------------------------------------------------------------
__global__ __launch_bounds__(256) void memb_kernel(
    const float* __restrict__ x, float4* __restrict__ out4)
{
    __shared__ float xs_t[D_SZ * MPAD];        // 20 KB, [i][m]
    __shared__ float es[MROWS * 65];
    __shared__ float sinv[MROWS];
    __shared__ int   s_last;

    const int row0 = blockIdx.x * MROWS;
    const int tid  = threadIdx.x;

    #pragma unroll
    for (int m = 0; m < MROWS; m++)
        xs_t[tid * MPAD + m] = x[(size_t)(row0 + m) * D_SZ + tid];

    // Zero this block's out slice: 16 rows x 256 cols = 1024 float4.
    {
        const float4 z = make_float4(0.f, 0.f, 0.f, 0.f);
        float4* oz = out4 + (size_t)row0 * (O_SZ / 4);
        #pragma unroll
        for (int k = 0; k < 4; k++)
            oz[tid + k * 256] = z;
    }
    __syncthreads();

    const int r    = tid & 63;
    const int msub = tid >> 6;                 // rows msub*4 .. +3

    ull acc2[2] = {0ull, 0ull};                // 0ull == (0.f, 0.f)

    #pragma unroll 8
    for (int i = 0; i < D_SZ; i++) {
        const ulonglong2 cf = *(const ulonglong2*)&g_coef[i * R_SZ + r];
        // cf.x = (-a,-a), cf.y = (b2,b2)
        const ulonglong2 xv = *(const ulonglong2*)&xs_t[i * MPAD + msub * 4];
        acc2[0] = fma2(xv.x, fma2(xv.x, cf.x, cf.y), acc2[0]);
        acc2[1] = fma2(xv.y, fma2(xv.y, cf.x, cf.y), acc2[1]);
    }

    const float cv = g_c[r];
    {
        const float2 v0 = unpack2(acc2[0]);
        const float2 v1 = unpack2(acc2[1]);
        es[(msub * 4 + 0) * 65 + r] = expf(v0.x - cv);
        es[(msub * 4 + 1) * 65 + r] = expf(v0.y - cv);
        es[(msub * 4 + 2) * 65 + r] = expf(v1.x - cv);
        es[(msub * 4 + 3) * 65 + r] = expf(v1.y - cv);
    }
    __syncthreads();

    if (tid < MROWS) {
        float s = 0.0f;
        #pragma unroll
        for (int rr = 0; rr < R_SZ; rr++) s += es[tid * 65 + rr];
        sinv[tid] = 1.0f / (s + 1e-8f);
    }
    __syncthreads();

    #pragma unroll
    for (int k = 0; k < 4; k++) {
        int idx = tid + k * 256;               // 1024 = 16 rows x 64 rules
        int m   = idx >> 6;
        int rr  = idx & 63;
        float e = es[m * 65 + rr];
        if (e != 0.0f) {
            int pos = atomicAdd(&g_count[rr], 1);
            g_lb[rr][pos] = row0 + m;
            g_lf[rr][pos] = e * sinv[m];
        }
    }

    // ---- fused builder: last block to retire emits the worklist ----
    __threadfence();
    __syncthreads();
    if (tid == 0)
        s_last = (atomicAdd(&g_done, 1) == (int)gridDim.x - 1);
    __syncthreads();
    if (s_last && tid < R_SZ) {
        const int cnt = g_count[tid];
        const int nd  = ((cnt + MCH - 1) / MCH) * 2;
        if (nd) {
            int base = atomicAdd(&g_nwork, nd);
            for (int j = 0; j < nd; j++)
                g_work[base + j] = (tid << 11) | j;
        }
    }
}

// ---------------------------------------------------------------------------
// Persistent expert blocks pop work items. Item = 16 rows x 128 o-cols of
// one rule. Thread = one o column; W prefetched in double-buffered groups of
// IUNR=16; x tile transposed in SMEM (4 broadcast LDS.128 per i).
// Exact R8 39.8us configuration — do not modify.
// ---------------------------------------------------------------------------
__global__ __launch_bounds__(128) void expert_kernel(
    const float* __restrict__ x,
    const float* __restrict__ W,
    const float* __restrict__ bias,
    float* __restrict__ out)
{
    __shared__ float xst[D_SZ * XPAD];         // 20 KB
    __shared__ int   sb[MCH];
    __shared__ float sf[MCH];
    __shared__ int   s_cur;

    const int tid   = threadIdx.x;
    const int nwork = g_nwork;

    while (true) {
        __syncthreads();                       // protect s_cur + smem reuse
        if (tid == 0) s_cur = atomicAdd(&g_fetch, 1);
        __syncthreads();
        const int cur = s_cur;
        if (cur >= nwork) return;

        const int desc = g_work[cur];
        const int r    = desc >> 11;
        const int half = desc & 1;
        const int c0   = ((desc >> 1) & 1023) * MCH;
        const int cnt  = g_count[r];

        if (tid < MCH) {
            int p = c0 + tid;
            int bb = 0; float ff = 0.0f;
            if (p < cnt) { bb = g_lb[r][p]; ff = g_lf[r][p]; }
            sb[tid] = bb; sf[tid] = ff;
        }
        __syncthreads();

        // Stage 16 x rows transposed: thread owns i = tid and i = tid+128.
        #pragma unroll
        for (int m = 0; m < MCH; m++) {
            const float* xr = x + (size_t)sb[m] * D_SZ;
            xst[tid * XPAD + m]         = xr[tid];
            xst[(tid + 128) * XPAD + m] = xr[tid + 128];
        }
        __syncthreads();

        const int    o  = half * 128 + tid;
        const float* Wp = W + ((size_t)r << 16) + o;
        const float  bv = bias[(r << 8) + o];

        float acc[MCH];
        #pragma unroll
        for (int m = 0; m < MCH; m++) acc[m] = 0.0f;

        float w[IUNR];
        #pragma unroll
        for (int k = 0; k < IUNR; k++) w[k] = Wp[k << 8];

        for (int i0 = 0; i0 < D_SZ; i0 += IUNR) {
            float wn[IUNR];
            const bool more = (i0 + IUNR) < D_SZ;
            #pragma unroll
            for (int k = 0; k < IUNR; k++)
                if (more) wn[k] = Wp[(i0 + IUNR + k) << 8];

            #pragma unroll
            for (int k = 0; k < IUNR; k++) {
                const float4* xp = (const float4*)&xst[(i0 + k) * XPAD];
                const float4 x0 = xp[0], x1 = xp[1], x2 = xp[2], x3 = xp[3];
                const float wk = w[k];
                acc[0]  = fmaf(wk, x0.x, acc[0]);
                acc[1]  = fmaf(wk, x0.y, acc[1]);
                acc[2]  = fmaf(wk, x0.z, acc[2]);
                acc[3]  = fmaf(wk, x0.w, acc[3]);
                acc[4]  = fmaf(wk, x1.x, acc[4]);
                acc[5]  = fmaf(wk, x1.y, acc[5]);
                acc[6]  = fmaf(wk, x1.z, acc[6]);
                acc[7]  = fmaf(wk, x1.w, acc[7]);
                acc[8]  = fmaf(wk, x2.x, acc[8]);
                acc[9]  = fmaf(wk, x2.y, acc[9]);
                acc[10] = fmaf(wk, x2.z, acc[10]);
                acc[11] = fmaf(wk, x2.w, acc[11]);
                acc[12] = fmaf(wk, x3.x, acc[12]);
                acc[13] = fmaf(wk, x3.y, acc[13]);
                acc[14] = fmaf(wk, x3.z, acc[14]);
                acc[15] = fmaf(wk, x3.w, acc[15]);
            }
            #pragma unroll
            for (int k = 0; k < IUNR; k++) w[k] = wn[k];
        }

        #pragma unroll
        for (int m = 0; m < MCH; m++) {
            const float f = sf[m];
            if (f != 0.0f)
                atomicAdd(&out[((size_t)sb[m] << 8) + o], f * (acc[m] + bv));
        }
    }
}

// ---------------------------------------------------------------------------
extern "C" void kernel_launch(void* const* d_in, const int* in_sizes, int n_in,
                              void* d_out, int out_size)
{
    const float* x   = (const float*)d_in[0];   // [8192, 256]
    const float* mu  = (const float*)d_in[1];   // [256, 64]
    const float* sig = (const float*)d_in[2];   // [256, 64]
    const float* W   = (const float*)d_in[3];   // [64, 256, 256]
    const float* b   = (const float*)d_in[4];   // [64, 256]
    float* out       = (float*)d_out;           // [8192, 256]

    setup_kernel<<<R_SZ, 256>>>(mu, sig);
    memb_kernel<<<B_SZ / MROWS, 256>>>(x, (float4*)out);
    expert_kernel<<<EGRID, 128>>>(x, W, b, out);
}

// round 17
// speedup vs baseline: 1.7717x; 1.7717x over previous
#include <cuda_runtime.h>

// ANFIS_61280593380167 — B=8192, D=256, R=64, O=256, fp32.
//
// out[b,o] = sum_r f[b,r] * (x[b,:] @ W[r] + b[r])
// f[b,r]   = frs[b,r] / (sum_r frs[b,r] + 1e-8),  frs = exp(-sum (x-mu)^2/(2 sig^2))
//
// frs underflows to exact fp32 zero for ~99% of (b,r) pairs (as in the
// reference); zero f contributes exactly zero. Compute f, compact nonzero
// (b,f) pairs per rule, build a worklist (fused into memb's last block),
// process with persistent expert blocks.
//
// All hot loops are scalar fmaf: fma.rn.f32x2 regressed in BOTH kernels
// (R7 expert, R16 memb) — 64-bit asm operands wreck allocation/scheduling.
// Expert keeps the R8-proven IUNR=16 double-buffer prefetch + dynamic queue;
// item granularity MCH=8 (halved) so ~1400 items pack the ~888 resident
// block slots instead of one straggling wave of ~700.

#define B_SZ 8192
#define D_SZ 256
#define R_SZ 64
#define O_SZ 256
#define MCH   8      // batch rows per expert chunk (fine granularity)
#define XPAD  12     // x-tile stride (floats) in expert (16B-aligned rows)
#define MROWS 16     // batch rows per memb block (512 blocks)
#define MPAD  20     // x-tile stride (floats) in memb (16B-aligned rows)
#define IUNR  16     // W prefetch depth (double-buffered groups)
#define EGRID 1184   // persistent expert blocks

// Scratch (__device__ globals: allocation-free rule)
__device__ int    g_count[R_SZ];
__device__ int    g_lb[R_SZ][B_SZ];
__device__ float  g_lf[R_SZ][B_SZ];
__device__ float2 g_ab[D_SZ * R_SZ];  // {a = 1/(2 sig^2), b2 = 2 mu a}
__device__ float  g_c [R_SZ];         // sum_i mu^2 a
__device__ int    g_work[R_SZ * (B_SZ / MCH) * 2];
__device__ int    g_nwork;
__device__ int    g_fetch;
__device__ int    g_done;

// ---------------------------------------------------------------------------
// Merged: zero output, reset counters, precompute coefficients.
// grid = 512: blocks 0..63 additionally run prep for rule r = blockIdx.x.
// ---------------------------------------------------------------------------
__global__ __launch_bounds__(256) void setup_kernel(
    float4* __restrict__ out4,
    const float* __restrict__ mu, const float* __restrict__ sig)
{
    const int tid = threadIdx.x;
    const int idx = blockIdx.x * 256 + tid;
    const float4 z = make_float4(0.f, 0.f, 0.f, 0.f);
    #pragma unroll
    for (int k = 0; k < 4; k++)
        out4[idx + k * 131072] = z;

    if (blockIdx.x == 64) {
        if (tid < R_SZ) g_count[tid] = 0;
        if (tid == R_SZ) { g_nwork = 0; g_fetch = 0; g_done = 0; }
        return;
    }
    if (blockIdx.x >= 64) return;

    const int r = blockIdx.x, i = tid;
    const float m = mu [i * R_SZ + r];
    const float s = sig[i * R_SZ + r];
    const float a = 0.5f / (s * s);
    g_ab[i * R_SZ + r] = make_float2(a, 2.0f * m * a);

    __shared__ float red[256];
    red[i] = m * m * a;
    __syncthreads();
    #pragma unroll
    for (int st = 128; st > 0; st >>= 1) {
        if (i < st) red[i] += red[i + st];
        __syncthreads();
    }
    if (i == 0) g_c[r] = red[0];
}

// ---------------------------------------------------------------------------
// Memberships + normalization + compaction. 16 rows / 256-thread block.
// x tile transposed ([i][m]): per i, one LDG.64 coeff + 1 broadcast LDS.128
// + 8 scalar FMAs for 4 rows. logit = sum_i x*fma(x,-a,b2) - c.
// Last block to retire also builds the expert worklist (fused builder).
// ---------------------------------------------------------------------------
__global__ __launch_bounds__(256) void memb_kernel(const float* __restrict__ x)
{
    __shared__ float xs_t[D_SZ * MPAD];        // 20 KB, [i][m]
    __shared__ float es[MROWS * 65];
    __shared__ float sinv[MROWS];
    __shared__ int   s_last;

    const int row0 = blockIdx.x * MROWS;
    const int tid  = threadIdx.x;

    #pragma unroll
    for (int m = 0; m < MROWS; m++)
        xs_t[tid * MPAD + m] = x[(size_t)(row0 + m) * D_SZ + tid];
    __syncthreads();

    const int r    = tid & 63;
    const int msub = tid >> 6;                 // rows msub*4 .. +3

    float acc[4];
    #pragma unroll
    for (int g = 0; g < 4; g++) acc[g] = 0.0f;

    #pragma unroll 8
    for (int i = 0; i < D_SZ; i++) {
        const float2 ab = g_ab[i * R_SZ + r];
        const float4 xv = *(const float4*)&xs_t[i * MPAD + msub * 4];
        acc[0] = fmaf(xv.x, fmaf(xv.x, -ab.x, ab.y), acc[0]);
        acc[1] = fmaf(xv.y, fmaf(xv.y, -ab.x, ab.y), acc[1]);
        acc[2] = fmaf(xv.z, fmaf(xv.z, -ab.x, ab.y), acc[2]);
        acc[3] = fmaf(xv.w, fmaf(xv.w, -ab.x, ab.y), acc[3]);
    }

    const float cv = g_c[r];
    #pragma unroll
    for (int g = 0; g < 4; g++)
        es[(msub * 4 + g) * 65 + r] = expf(acc[g] - cv);
    __syncthreads();

    if (tid < MROWS) {
        float s = 0.0f;
        #pragma unroll
        for (int rr = 0; rr < R_SZ; rr++) s += es[tid * 65 + rr];
        sinv[tid] = 1.0f / (s + 1e-8f);
    }
    __syncthreads();

    #pragma unroll
    for (int k = 0; k < 4; k++) {
        int idx = tid + k * 256;               // 1024 = 16 rows x 64 rules
        int m   = idx >> 6;
        int rr  = idx & 63;
        float e = es[m * 65 + rr];
        if (e != 0.0f) {
            int pos = atomicAdd(&g_count[rr], 1);
            g_lb[rr][pos] = row0 + m;
            g_lf[rr][pos] = e * sinv[m];
        }
    }

    // ---- fused builder: last block to retire emits the worklist ----
    __threadfence();
    __syncthreads();
    if (tid == 0)
        s_last = (atomicAdd(&g_done, 1) == (int)gridDim.x - 1);
    __syncthreads();
    if (s_last && tid < R_SZ) {
        const int cnt = g_count[tid];
        const int nd  = ((cnt + MCH - 1) / MCH) * 2;
        if (nd) {
            int base = atomicAdd(&g_nwork, nd);
            for (int j = 0; j < nd; j++)
                g_work[base + j] = (tid << 11) | j;
        }
    }
}

// ---------------------------------------------------------------------------
// Persistent expert blocks pop work items. Item = 8 rows x 128 o-cols of
// one rule. Thread = one o column; W prefetched in double-buffered groups of
// IUNR=16; x tile transposed in SMEM (2 broadcast LDS.128 per i).
// ---------------------------------------------------------------------------
__global__ __launch_bounds__(128) void expert_kernel(
    const float* __restrict__ x,
    const float* __restrict__ W,
    const float* __restrict__ bias,
    float* __restrict__ out)
{
    __shared__ float xst[D_SZ * XPAD];         // 12 KB
    __shared__ int   sb[MCH];
    __shared__ float sf[MCH];
    __shared__ int   s_cur;

    const int tid   = threadIdx.x;
    const int nwork = g_nwork;

    while (true) {
        __syncthreads();                       // protect s_cur + smem reuse
        if (tid == 0) s_cur = atomicAdd(&g_fetch, 1);
        __syncthreads();
        const int cur = s_cur;
        if (cur >= nwork) return;

        const int desc = g_work[cur];
        const int r    = desc >> 11;
        const int half = desc & 1;
        const int c0   = ((desc >> 1) & 1023) * MCH;
        const int cnt  = g_count[r];

        if (tid < MCH) {
            int p = c0 + tid;
            int bb = 0; float ff = 0.0f;
            if (p < cnt) { bb = g_lb[r][p]; ff = g_lf[r][p]; }
            sb[tid] = bb; sf[tid] = ff;
        }
        __syncthreads();

        // Stage 8 x rows transposed: thread owns i = tid and i = tid+128.
        #pragma unroll
        for (int m = 0; m < MCH; m++) {
            const float* xr = x + (size_t)sb[m] * D_SZ;
            xst[tid * XPAD + m]         = xr[tid];
            xst[(tid + 128) * XPAD + m] = xr[tid + 128];
        }
        __syncthreads();

        const int    o  = half * 128 + tid;
        const float* Wp = W + ((size_t)r << 16) + o;
        const float  bv = bias[(r << 8) + o];

        float acc[MCH];
        #pragma unroll
        for (int m = 0; m < MCH; m++) acc[m] = 0.0f;

        float w[IUNR];
        #pragma unroll
        for (int k = 0; k < IUNR; k++) w[k] = Wp[k << 8];

        for (int i0 = 0; i0 < D_SZ; i0 += IUNR) {
            float wn[IUNR];
            const bool more = (i0 + IUNR) < D_SZ;
            #pragma unroll
            for (int k = 0; k < IUNR; k++)
                if (more) wn[k] = Wp[(i0 + IUNR + k) << 8];

            #pragma unroll
            for (int k = 0; k < IUNR; k++) {
                const float4* xp = (const float4*)&xst[(i0 + k) * XPAD];
                const float4 x0 = xp[0], x1 = xp[1];
                const float wk = w[k];
                acc[0] = fmaf(wk, x0.x, acc[0]);
                acc[1] = fmaf(wk, x0.y, acc[1]);
                acc[2] = fmaf(wk, x0.z, acc[2]);
                acc[3] = fmaf(wk, x0.w, acc[3]);
                acc[4] = fmaf(wk, x1.x, acc[4]);
                acc[5] = fmaf(wk, x1.y, acc[5]);
                acc[6] = fmaf(wk, x1.z, acc[6]);
                acc[7] = fmaf(wk, x1.w, acc[7]);
            }
            #pragma unroll
            for (int k = 0; k < IUNR; k++) w[k] = wn[k];
        }

        #pragma unroll
        for (int m = 0; m < MCH; m++) {
            const float f = sf[m];
            if (f != 0.0f)
                atomicAdd(&out[((size_t)sb[m] << 8) + o], f * (acc[m] + bv));
        }
    }
}

// ---------------------------------------------------------------------------
extern "C" void kernel_launch(void* const* d_in, const int* in_sizes, int n_in,
                              void* d_out, int out_size)
{
    const float* x   = (const float*)d_in[0];   // [8192, 256]
    const float* mu  = (const float*)d_in[1];   // [256, 64]
    const float* sig = (const float*)d_in[2];   // [256, 64]
    const float* W   = (const float*)d_in[3];   // [64, 256, 256]
    const float* b   = (const float*)d_in[4];   // [64, 256]
    float* out       = (float*)d_out;           // [8192, 256]

    setup_kernel<<<512, 256>>>((float4*)out, mu, sig);
    memb_kernel<<<B_SZ / MROWS, 256>>>(x);
    expert_kernel<<<EGRID, 128>>>(x, W, b, out);
}